// round 9
// baseline (speedup 1.0000x reference)
#include <cuda_runtime.h>
#include <cuda_fp16.h>
#include <cstdint>

#define NN 20000
#define NE 160000
#define HD 1024
#define NG 16
#define EPSV 1e-5f
#define SLOPE 0.01f

// ---- device scratch (no allocs allowed) ----
__device__ float   d_h  [(size_t)NN * HD];
__device__ float   d_t  [(size_t)NN * HD];
__device__ __half  d_ahi[(size_t)NN * HD];
__device__ __half  d_alo[(size_t)NN * HD];
__device__ __half  d_w2hi[HD * HD], d_w2lo[HD * HD];
__device__ __half  d_w3hi[HD * HD], d_w3lo[HD * HD];
__device__ int     d_cnt[NN], d_offs[NN + 1], d_cur[NN], d_csr[NE];
__device__ float   d_dinv[NN], d_s[NN];
__device__ int     d_bstart[NG + 1];
__device__ float   d_pool[NG * HD];
__device__ float   d_o1[NG * 256];

__device__ __forceinline__ float warp_sum(float v) {
    #pragma unroll
    for (int o = 16; o; o >>= 1) v += __shfl_xor_sync(0xffffffffu, v, o);
    return v;
}

// ---- graph preprocessing ----
__global__ void k_init() {
    int i = blockIdx.x * blockDim.x + threadIdx.x;
    if (i < NN) d_cnt[i] = 0;
}
__global__ void k_count(const int* __restrict__ ei) {
    int e = blockIdx.x * blockDim.x + threadIdx.x;
    if (e < NE) atomicAdd(&d_cnt[ei[NE + e]], 1);
}
__global__ void k_dinv() {
    int n = blockIdx.x * blockDim.x + threadIdx.x;
    if (n < NN) d_dinv[n] = rsqrtf((float)(d_cnt[n] + 1));
}
__global__ void k_scan() {   // single-block exclusive scan
    __shared__ int sh[1024];
    __shared__ int carry_sh;
    int tid = threadIdx.x;
    if (tid == 0) carry_sh = 0;
    __syncthreads();
    for (int base = 0; base < NN; base += 1024) {
        int i = base + tid;
        int v = (i < NN) ? d_cnt[i] : 0;
        sh[tid] = v;
        __syncthreads();
        #pragma unroll
        for (int off = 1; off < 1024; off <<= 1) {
            int t = (tid >= off) ? sh[tid - off] : 0;
            __syncthreads();
            sh[tid] += t;
            __syncthreads();
        }
        int carry = carry_sh;
        if (i < NN) { int ex = carry + sh[tid] - v; d_offs[i] = ex; d_cur[i] = ex; }
        __syncthreads();
        if (tid == 0) carry_sh = carry + sh[1023];
        __syncthreads();
    }
    if (tid == 0) d_offs[NN] = carry_sh;
}
__global__ void k_fill(const int* __restrict__ ei) {
    int e = blockIdx.x * blockDim.x + threadIdx.x;
    if (e < NE) d_csr[atomicAdd(&d_cur[ei[NE + e]], 1)] = ei[e];
}

// layer-1 scalar aggregation (IN=1 makes conv1 rank-1)
__global__ void k_s(const float* __restrict__ x) {
    int n = blockIdx.x * blockDim.x + threadIdx.x;
    if (n >= NN) return;
    float dv = d_dinv[n];
    float acc = dv * x[n];
    int b = d_offs[n], e = d_offs[n + 1];
    for (int j = b; j < e; j++) { int s = d_csr[j]; acc += d_dinv[s] * x[s]; }
    d_s[n] = dv * acc;
}
__global__ void k_t1(const float* __restrict__ W1) {
    int i = blockIdx.x * blockDim.x + threadIdx.x;
    if (i < NN * HD) d_t[i] = d_s[i >> 10] * W1[i & 1023];
}

// W^T + fp16 hi/lo split: out[n*HD+k] = split(W[k*HD+n])
__global__ void k_wsplit(const float* __restrict__ W, int which) {
    __half* hi = (which == 2) ? d_w2hi : d_w3hi;
    __half* lo = (which == 2) ? d_w2lo : d_w3lo;
    __shared__ float tile[32][33];
    int bx = blockIdx.x * 32, by = blockIdx.y * 32;
    int tx = threadIdx.x, ty = threadIdx.y;
    for (int r = ty; r < 32; r += 8)
        tile[r][tx] = W[(size_t)(by + r) * HD + bx + tx];
    __syncthreads();
    for (int r = ty; r < 32; r += 8) {
        float w = tile[tx][r];
        __half h = __float2half_rn(w);
        size_t o = (size_t)(bx + r) * HD + by + tx;
        hi[o] = h;
        lo[o] = __float2half_rn(w - __half2float(h));
    }
}

// LN + LeakyReLU: h = act(LN(t + bias)*g + be)
__global__ void k_ln_act(const float* __restrict__ bias,
                         const float* __restrict__ gam,
                         const float* __restrict__ bet) {
    int n = blockIdx.x, tid = threadIdx.x;
    int wid = tid >> 5, lane = tid & 31;
    float v[4], s = 0.f, sq = 0.f;
    #pragma unroll
    for (int k = 0; k < 4; k++) {
        int c = tid + k * 256;
        float xv = d_t[(size_t)n * HD + c] + bias[c];
        v[k] = xv; s += xv; sq += xv * xv;
    }
    s = warp_sum(s); sq = warp_sum(sq);
    __shared__ float shs[8], shq[8];
    if (lane == 0) { shs[wid] = s; shq[wid] = sq; }
    __syncthreads();
    if (wid == 0) {
        float a = (lane < 8) ? shs[lane] : 0.f;
        float b = (lane < 8) ? shq[lane] : 0.f;
        a = warp_sum(a); b = warp_sum(b);
        if (lane == 0) { shs[0] = a; shq[0] = b; }
    }
    __syncthreads();
    float mu = shs[0] * (1.f / HD);
    float var = shq[0] * (1.f / HD) - mu * mu;
    float r = rsqrtf(var + EPSV);
    #pragma unroll
    for (int k = 0; k < 4; k++) {
        int c = tid + k * 256;
        float y = (v[k] - mu) * r * gam[c] + bet[c];
        d_h[(size_t)n * HD + c] = (y >= 0.f) ? y : SLOPE * y;
    }
}

// aggregation of d_h -> fp16 hi/lo (one block per node)
__global__ void k_agg() {
    int dd = blockIdx.x, tid = threadIdx.x;
    float dv = d_dinv[dd];
    float acc[4];
    #pragma unroll
    for (int k = 0; k < 4; k++)
        acc[k] = dv * d_h[(size_t)dd * HD + tid + k * 256];
    int b = d_offs[dd], e = d_offs[dd + 1];
    for (int j = b; j < e; j++) {
        int s = d_csr[j];
        float w = d_dinv[s];
        const float* hr = &d_h[(size_t)s * HD];
        #pragma unroll
        for (int k = 0; k < 4; k++) acc[k] += w * hr[tid + k * 256];
    }
    #pragma unroll
    for (int k = 0; k < 4; k++) {
        int c = tid + k * 256;
        float o = dv * acc[k];
        __half h = __float2half_rn(o);
        d_ahi[(size_t)dd * HD + c] = h;
        d_alo[(size_t)dd * HD + c] = __float2half_rn(o - __half2float(h));
    }
}

// ---- mma.sync GEMM: d_t = Agg @ W  (2 products: (a_hi+a_lo)*b_hi) ----
// XOR-swizzled smem (pitch 64B, chunk p = ch ^ ((row>>1)&3)) — conflict-free
// for both cp.async store phases and ldmatrix read phases. 4-stage pipeline.
#define BM 128
#define BN 128
#define BK 32
#define KIT (HD / BK)          // 32
#define STAGES 4
#define ARR_B (BM * 64)        // 8192 bytes per array (128 rows x 64B)
#define STAGE_B (3 * ARR_B)    // 24576 bytes per stage (A_hi, A_lo, B)
#define GEMM_SMEM (STAGES * STAGE_B)   // 98304

__device__ __forceinline__ void cp16(uint32_t saddr, const void* g, int sz) {
    asm volatile("cp.async.cg.shared.global [%0], [%1], 16, %2;"
                 :: "r"(saddr), "l"(g), "r"(sz));
}
#define CP_COMMIT() asm volatile("cp.async.commit_group;" ::: "memory")
#define CP_WAIT2()  asm volatile("cp.async.wait_group 2;" ::: "memory")

#define LDSM4(r, addr)                                                          \
    asm volatile("ldmatrix.sync.aligned.m8n8.x4.shared.b16 {%0,%1,%2,%3}, [%4];"\
                 : "=r"((r)[0]), "=r"((r)[1]), "=r"((r)[2]), "=r"((r)[3])       \
                 : "r"(addr))

#define MMA16816(c, a, b0, b1)                                                  \
    asm volatile("mma.sync.aligned.m16n8k16.row.col.f32.f16.f16.f32 "           \
                 "{%0,%1,%2,%3}, {%4,%5,%6,%7}, {%8,%9}, {%0,%1,%2,%3};"        \
                 : "+f"((c)[0]), "+f"((c)[1]), "+f"((c)[2]), "+f"((c)[3])       \
                 : "r"((a)[0]), "r"((a)[1]), "r"((a)[2]), "r"((a)[3]),          \
                   "r"(b0), "r"(b1))

__device__ __forceinline__ void g_load_stage(
    int it, int s, uint32_t sbase, int tid, int m0, int n0,
    const __half* ahi, const __half* alo, const __half* bhi)
{
    int k0 = it * BK;
    uint32_t sb = sbase + s * STAGE_B;
    int row = tid >> 2, ch = tid & 3;
    int p = ch ^ ((row >> 1) & 3);                 // XOR swizzle
    uint32_t so = (uint32_t)(row * 64 + p * 16);
    int gr = m0 + row;
    int asz = (gr < NN) ? 16 : 0;
    size_t aoff = ((size_t)((gr < NN) ? gr : 0) << 10) + k0 + ch * 8;
    cp16(sb + 0 * ARR_B + so, ahi + aoff, asz);
    cp16(sb + 1 * ARR_B + so, alo + aoff, asz);
    size_t boff = ((size_t)(n0 + row) << 10) + k0 + ch * 8;
    cp16(sb + 2 * ARR_B + so, bhi + boff, 16);
}

__global__ void __launch_bounds__(512, 1) k_gemm(int which) {
    extern __shared__ char smem[];
    const __half* whi = (which == 2) ? d_w2hi : d_w3hi;
    uint32_t sbase = (uint32_t)__cvta_generic_to_shared(smem);
    int tid = threadIdx.x;
    int lane = tid & 31, wid = tid >> 5;
    int warp_m = wid & 3, warp_n = wid >> 2;
    int m0 = blockIdx.x * BM, n0 = blockIdx.y * BN;

    float acc[2][4][4];
    #pragma unroll
    for (int mt = 0; mt < 2; mt++)
        #pragma unroll
        for (int nt = 0; nt < 4; nt++)
            #pragma unroll
            for (int q = 0; q < 4; q++) acc[mt][nt][q] = 0.f;

    // per-lane swizzle-invariant constants
    int la = lane & 15;
    uint32_t a_row = (uint32_t)((warp_m * 32 + la) * 64);
    int swa = (la >> 1) & 3;
    int acb = lane >> 4;                            // logical chunk base 0/1
    int rb = (lane & 7) | ((lane >> 4) << 3);
    uint32_t b_row = (uint32_t)((warp_n * 32 + rb) * 64);
    int swb = (rb >> 1) & 3;
    int bcb = (lane >> 3) & 1;

    g_load_stage(0, 0, sbase, tid, m0, n0, d_ahi, d_alo, whi);
    CP_COMMIT();
    g_load_stage(1, 1, sbase, tid, m0, n0, d_ahi, d_alo, whi);
    CP_COMMIT();
    g_load_stage(2, 2, sbase, tid, m0, n0, d_ahi, d_alo, whi);
    CP_COMMIT();

    for (int it = 0; it < KIT; ++it) {
        CP_WAIT2();
        __syncthreads();
        if (it + 3 < KIT)
            g_load_stage(it + 3, (it + 3) & 3, sbase, tid, m0, n0, d_ahi, d_alo, whi);
        CP_COMMIT();

        uint32_t sb = sbase + (it & 3) * STAGE_B;
        #pragma unroll
        for (int kk = 0; kk < 2; kk++) {
            uint32_t ah[2][4], al[2][4], bh[2][4];
            int pa = (acb | (kk << 1)) ^ swa;
            int pb = (bcb | (kk << 1)) ^ swb;
            #pragma unroll
            for (int mt = 0; mt < 2; mt++) {
                uint32_t ad = sb + a_row + (uint32_t)(mt * 1024 + pa * 16);
                LDSM4(ah[mt], ad);
                LDSM4(al[mt], ad + ARR_B);
            }
            #pragma unroll
            for (int p = 0; p < 2; p++) {
                uint32_t bd = sb + 2 * ARR_B + b_row + (uint32_t)(p * 1024 + pb * 16);
                LDSM4(bh[p], bd);
            }
            #pragma unroll
            for (int mt = 0; mt < 2; mt++)
                #pragma unroll
                for (int nt = 0; nt < 4; nt++) {
                    int p = nt >> 1, q = (nt & 1) * 2;
                    MMA16816(acc[mt][nt], ah[mt], bh[p][q], bh[p][q + 1]);
                    MMA16816(acc[mt][nt], al[mt], bh[p][q], bh[p][q + 1]);
                }
        }
        __syncthreads();
    }

    // epilogue: c-frag (row=t/4, col=2*(t%4))
    int mrow = m0 + warp_m * 32 + (lane >> 2);
    int ncol = n0 + warp_n * 32 + (lane & 3) * 2;
    #pragma unroll
    for (int mt = 0; mt < 2; mt++)
        #pragma unroll
        for (int nt = 0; nt < 4; nt++) {
            int r1 = mrow + mt * 16, r2 = r1 + 8;
            int c = ncol + nt * 8;
            if (r1 < NN) {
                float2 v = make_float2(acc[mt][nt][0], acc[mt][nt][1]);
                *reinterpret_cast<float2*>(&d_t[((size_t)r1 << 10) + c]) = v;
            }
            if (r2 < NN) {
                float2 v = make_float2(acc[mt][nt][2], acc[mt][nt][3]);
                *reinterpret_cast<float2*>(&d_t[((size_t)r2 << 10) + c]) = v;
            }
        }
}

// ---- pooling + FC head ----
__global__ void k_bstart(const int* __restrict__ batch) {
    int g = threadIdx.x;
    if (g > NG) return;
    int lo = 0, hi = NN;
    while (lo < hi) { int m = (lo + hi) >> 1; if (batch[m] < g) lo = m + 1; else hi = m; }
    d_bstart[g] = lo;
}
__global__ void k_pool() {
    int g = blockIdx.x, col = blockIdx.y * 128 + threadIdx.x;
    int b = d_bstart[g], e = d_bstart[g + 1];
    float s = 0.f;
    for (int n = b; n < e; n++) s += d_h[(size_t)n * HD + col];
    d_pool[g * HD + col] = s / fmaxf((float)(e - b), 1.0f);
}
__global__ void k_fc1(const float* __restrict__ fw1, const float* __restrict__ fb1) {
    int g = blockIdx.x, j = threadIdx.x;
    float acc = fb1[j];
    for (int k = 0; k < HD; k++) acc += d_pool[g * HD + k] * fw1[k * 256 + j];
    d_o1[g * 256 + j] = acc;
}
__global__ void k_fc2(const float* __restrict__ fw2, const float* __restrict__ fb2,
                      float* __restrict__ out) {
    int g = blockIdx.x, j = threadIdx.x;   // 256 threads
    float v = d_o1[g * 256 + j] * fw2[j];
    v = warp_sum(v);
    __shared__ float sh[8];
    if ((j & 31) == 0) sh[j >> 5] = v;
    __syncthreads();
    if (j == 0) {
        float a = 0.f;
        for (int w = 0; w < 8; w++) a += sh[w];
        out[g] = a + fb2[0];
    }
}

extern "C" void kernel_launch(void* const* d_in, const int* in_sizes, int n_in,
                              void* d_out, int out_size) {
    const float* x    = (const float*)d_in[0];
    const int*   ei   = (const int*)  d_in[1];
    const int*   bat  = (const int*)  d_in[2];
    const float* W1   = (const float*)d_in[3];
    const float* b1   = (const float*)d_in[4];
    const float* W2   = (const float*)d_in[5];
    const float* b2   = (const float*)d_in[6];
    const float* W3   = (const float*)d_in[7];
    const float* b3   = (const float*)d_in[8];
    const float* g1   = (const float*)d_in[9];
    const float* be1  = (const float*)d_in[10];
    const float* g2   = (const float*)d_in[11];
    const float* be2  = (const float*)d_in[12];
    const float* g3   = (const float*)d_in[13];
    const float* be3  = (const float*)d_in[14];
    const float* fw1  = (const float*)d_in[15];
    const float* fb1  = (const float*)d_in[16];
    const float* fw2  = (const float*)d_in[17];
    const float* fb2  = (const float*)d_in[18];
    float* out = (float*)d_out;

    cudaFuncSetAttribute(k_gemm, cudaFuncAttributeMaxDynamicSharedMemorySize, GEMM_SMEM);

    k_init<<<(NN + 255) / 256, 256>>>();
    k_count<<<(NE + 255) / 256, 256>>>(ei);
    k_dinv<<<(NN + 255) / 256, 256>>>();
    k_scan<<<1, 1024>>>();
    k_fill<<<(NE + 255) / 256, 256>>>(ei);
    k_s<<<(NN + 255) / 256, 256>>>(x);
    k_t1<<<(NN * HD + 255) / 256, 256>>>(W1);
    dim3 wg(HD / 32, HD / 32), wb(32, 8);
    k_wsplit<<<wg, wb>>>(W2, 2);
    k_wsplit<<<wg, wb>>>(W3, 3);

    dim3 gg((NN + BM - 1) / BM, HD / BN);

    k_ln_act<<<NN, 256>>>(b1, g1, be1);
    k_agg<<<NN, 256>>>();
    k_gemm<<<gg, 512, GEMM_SMEM>>>(2);
    k_ln_act<<<NN, 256>>>(b2, g2, be2);
    k_agg<<<NN, 256>>>();
    k_gemm<<<gg, 512, GEMM_SMEM>>>(3);
    k_ln_act<<<NN, 256>>>(b3, g3, be3);

    k_bstart<<<1, 32>>>(bat);
    k_pool<<<dim3(NG, HD / 128), 128>>>();
    k_fc1<<<NG, 256>>>(fw1, fb1);
    k_fc2<<<NG, 256>>>(fw2, fb2, out);
}

// round 10
// speedup vs baseline: 1.0606x; 1.0606x over previous
#include <cuda_runtime.h>
#include <cuda_fp16.h>
#include <cstdint>

#define NN 20000
#define NE 160000
#define HD 1024
#define NG 16
#define EPSV 1e-5f
#define SLOPE 0.01f

// ---- device scratch (no allocs allowed) ----
__device__ float   d_h  [(size_t)NN * HD];
__device__ float   d_t  [(size_t)NN * HD];
__device__ __half  d_ahi[(size_t)NN * HD];
__device__ __half  d_alo[(size_t)NN * HD];
__device__ __half  d_w2hi[HD * HD], d_w2lo[HD * HD];
__device__ __half  d_w3hi[HD * HD], d_w3lo[HD * HD];
__device__ int     d_cnt[NN], d_offs[NN + 1], d_cur[NN], d_csr[NE];
__device__ float   d_dinv[NN], d_s[NN];
__device__ int     d_bstart[NG + 1];
__device__ float   d_pool[NG * HD];
__device__ float   d_o1[NG * 256];

__device__ __forceinline__ float warp_sum(float v) {
    #pragma unroll
    for (int o = 16; o; o >>= 1) v += __shfl_xor_sync(0xffffffffu, v, o);
    return v;
}

// ---- graph preprocessing ----
__global__ void k_init() {
    int i = blockIdx.x * blockDim.x + threadIdx.x;
    if (i < NN) d_cnt[i] = 0;
}
__global__ void k_count(const int* __restrict__ ei) {
    int e = blockIdx.x * blockDim.x + threadIdx.x;
    if (e < NE) atomicAdd(&d_cnt[ei[NE + e]], 1);
}
__global__ void k_dinv() {
    int n = blockIdx.x * blockDim.x + threadIdx.x;
    if (n < NN) d_dinv[n] = rsqrtf((float)(d_cnt[n] + 1));
}
__global__ void k_scan() {   // single-block exclusive scan
    __shared__ int sh[1024];
    __shared__ int carry_sh;
    int tid = threadIdx.x;
    if (tid == 0) carry_sh = 0;
    __syncthreads();
    for (int base = 0; base < NN; base += 1024) {
        int i = base + tid;
        int v = (i < NN) ? d_cnt[i] : 0;
        sh[tid] = v;
        __syncthreads();
        #pragma unroll
        for (int off = 1; off < 1024; off <<= 1) {
            int t = (tid >= off) ? sh[tid - off] : 0;
            __syncthreads();
            sh[tid] += t;
            __syncthreads();
        }
        int carry = carry_sh;
        if (i < NN) { int ex = carry + sh[tid] - v; d_offs[i] = ex; d_cur[i] = ex; }
        __syncthreads();
        if (tid == 0) carry_sh = carry + sh[1023];
        __syncthreads();
    }
    if (tid == 0) d_offs[NN] = carry_sh;
}
__global__ void k_fill(const int* __restrict__ ei) {
    int e = blockIdx.x * blockDim.x + threadIdx.x;
    if (e < NE) d_csr[atomicAdd(&d_cur[ei[NE + e]], 1)] = ei[e];
}

// layer-1 scalar aggregation (IN=1 makes conv1 rank-1)
__global__ void k_s(const float* __restrict__ x) {
    int n = blockIdx.x * blockDim.x + threadIdx.x;
    if (n >= NN) return;
    float dv = d_dinv[n];
    float acc = dv * x[n];
    int b = d_offs[n], e = d_offs[n + 1];
    for (int j = b; j < e; j++) { int s = d_csr[j]; acc += d_dinv[s] * x[s]; }
    d_s[n] = dv * acc;
}
__global__ void k_t1(const float* __restrict__ W1) {
    int i = blockIdx.x * blockDim.x + threadIdx.x;
    if (i < NN * HD) d_t[i] = d_s[i >> 10] * W1[i & 1023];
}

// W^T + fp16 hi/lo split: out[n*HD+k] = split(W[k*HD+n])
__global__ void k_wsplit(const float* __restrict__ W, int which) {
    __half* hi = (which == 2) ? d_w2hi : d_w3hi;
    __half* lo = (which == 2) ? d_w2lo : d_w3lo;
    __shared__ float tile[32][33];
    int bx = blockIdx.x * 32, by = blockIdx.y * 32;
    int tx = threadIdx.x, ty = threadIdx.y;
    for (int r = ty; r < 32; r += 8)
        tile[r][tx] = W[(size_t)(by + r) * HD + bx + tx];
    __syncthreads();
    for (int r = ty; r < 32; r += 8) {
        float w = tile[tx][r];
        __half h = __float2half_rn(w);
        size_t o = (size_t)(bx + r) * HD + by + tx;
        hi[o] = h;
        lo[o] = __float2half_rn(w - __half2float(h));
    }
}

// LN + LeakyReLU: h = act(LN(t + bias)*g + be)
__global__ void k_ln_act(const float* __restrict__ bias,
                         const float* __restrict__ gam,
                         const float* __restrict__ bet) {
    int n = blockIdx.x, tid = threadIdx.x;
    int wid = tid >> 5, lane = tid & 31;
    float v[4], s = 0.f, sq = 0.f;
    #pragma unroll
    for (int k = 0; k < 4; k++) {
        int c = tid + k * 256;
        float xv = d_t[(size_t)n * HD + c] + bias[c];
        v[k] = xv; s += xv; sq += xv * xv;
    }
    s = warp_sum(s); sq = warp_sum(sq);
    __shared__ float shs[8], shq[8];
    if (lane == 0) { shs[wid] = s; shq[wid] = sq; }
    __syncthreads();
    if (wid == 0) {
        float a = (lane < 8) ? shs[lane] : 0.f;
        float b = (lane < 8) ? shq[lane] : 0.f;
        a = warp_sum(a); b = warp_sum(b);
        if (lane == 0) { shs[0] = a; shq[0] = b; }
    }
    __syncthreads();
    float mu = shs[0] * (1.f / HD);
    float var = shq[0] * (1.f / HD) - mu * mu;
    float r = rsqrtf(var + EPSV);
    #pragma unroll
    for (int k = 0; k < 4; k++) {
        int c = tid + k * 256;
        float y = (v[k] - mu) * r * gam[c] + bet[c];
        d_h[(size_t)n * HD + c] = (y >= 0.f) ? y : SLOPE * y;
    }
}

// aggregation of d_h -> fp16 hi/lo (one block per node)
__global__ void k_agg() {
    int dd = blockIdx.x, tid = threadIdx.x;
    float dv = d_dinv[dd];
    float acc[4];
    #pragma unroll
    for (int k = 0; k < 4; k++)
        acc[k] = dv * d_h[(size_t)dd * HD + tid + k * 256];
    int b = d_offs[dd], e = d_offs[dd + 1];
    for (int j = b; j < e; j++) {
        int s = d_csr[j];
        float w = d_dinv[s];
        const float* hr = &d_h[(size_t)s * HD];
        #pragma unroll
        for (int k = 0; k < 4; k++) acc[k] += w * hr[tid + k * 256];
    }
    #pragma unroll
    for (int k = 0; k < 4; k++) {
        int c = tid + k * 256;
        float o = dv * acc[k];
        __half h = __float2half_rn(o);
        d_ahi[(size_t)dd * HD + c] = h;
        d_alo[(size_t)dd * HD + c] = __float2half_rn(o - __half2float(h));
    }
}

// ---- mma.sync GEMM: d_t = Agg @ W  (2 products: (a_hi+a_lo)*b_hi) ----
// 256-thread CTA, BM=64 x BN=128, XOR-swizzled smem, 4 stages, 16KB/stage
// -> 64KB smem/CTA -> up to 3 CTAs/SM for cross-CTA latency hiding.
#define BM 64
#define BN 128
#define BK 32
#define KIT (HD / BK)          // 32
#define STAGES 4
#define ARR_A (BM * 64)        // 4096 bytes per A array (64 rows x 64B)
#define ARR_BB (BN * 64)       // 8192 bytes for B array
#define STAGE_B (2 * ARR_A + ARR_BB)   // 16384 bytes per stage
#define GEMM_SMEM (STAGES * STAGE_B)   // 65536

__device__ __forceinline__ void cp16(uint32_t saddr, const void* g, int sz) {
    asm volatile("cp.async.cg.shared.global [%0], [%1], 16, %2;"
                 :: "r"(saddr), "l"(g), "r"(sz));
}
#define CP_COMMIT() asm volatile("cp.async.commit_group;" ::: "memory")
#define CP_WAIT2()  asm volatile("cp.async.wait_group 2;" ::: "memory")

#define LDSM4(r, addr)                                                          \
    asm volatile("ldmatrix.sync.aligned.m8n8.x4.shared.b16 {%0,%1,%2,%3}, [%4];"\
                 : "=r"((r)[0]), "=r"((r)[1]), "=r"((r)[2]), "=r"((r)[3])       \
                 : "r"(addr))

#define MMA16816(c, a, b0, b1)                                                  \
    asm volatile("mma.sync.aligned.m16n8k16.row.col.f32.f16.f16.f32 "           \
                 "{%0,%1,%2,%3}, {%4,%5,%6,%7}, {%8,%9}, {%0,%1,%2,%3};"        \
                 : "+f"((c)[0]), "+f"((c)[1]), "+f"((c)[2]), "+f"((c)[3])       \
                 : "r"((a)[0]), "r"((a)[1]), "r"((a)[2]), "r"((a)[3]),          \
                   "r"(b0), "r"(b1))

__device__ __forceinline__ void g_load_stage(
    int it, int s, uint32_t sbase, int tid, int m0, int n0,
    const __half* ahi, const __half* alo, const __half* bhi)
{
    int k0 = it * BK;
    uint32_t sb = sbase + s * STAGE_B;
    int row = tid >> 2, ch = tid & 3;              // row 0..63, ch 0..3
    int p = ch ^ ((row >> 1) & 3);                 // XOR swizzle
    uint32_t so = (uint32_t)(row * 64 + p * 16);
    // A hi + A lo (64 rows each)
    int gr = m0 + row;
    int asz = (gr < NN) ? 16 : 0;
    size_t aoff = ((size_t)((gr < NN) ? gr : 0) << 10) + k0 + ch * 8;
    cp16(sb + 0 * ARR_A + so, ahi + aoff, asz);
    cp16(sb + 1 * ARR_A + so, alo + aoff, asz);
    // B: 128 rows, two per thread (row, row+64)
    size_t boff = ((size_t)(n0 + row) << 10) + k0 + ch * 8;
    cp16(sb + 2 * ARR_A + so, bhi + boff, 16);
    int row2 = row + 64;
    int p2 = ch ^ ((row2 >> 1) & 3);
    uint32_t so2 = (uint32_t)(row2 * 64 + p2 * 16);
    size_t boff2 = ((size_t)(n0 + row2) << 10) + k0 + ch * 8;
    cp16(sb + 2 * ARR_A + so2, bhi + boff2, 16);
}

__global__ void __launch_bounds__(256) k_gemm(int which) {
    extern __shared__ char smem[];
    const __half* whi = (which == 2) ? d_w2hi : d_w3hi;
    uint32_t sbase = (uint32_t)__cvta_generic_to_shared(smem);
    int tid = threadIdx.x;
    int lane = tid & 31, wid = tid >> 5;
    int warp_m = wid & 1, warp_n = wid >> 1;       // 2 x 4 warp grid
    int m0 = blockIdx.x * BM, n0 = blockIdx.y * BN;

    float acc[2][4][4];
    #pragma unroll
    for (int mt = 0; mt < 2; mt++)
        #pragma unroll
        for (int nt = 0; nt < 4; nt++)
            #pragma unroll
            for (int q = 0; q < 4; q++) acc[mt][nt][q] = 0.f;

    // per-lane swizzle-invariant constants
    int la = lane & 15;
    uint32_t a_row = (uint32_t)((warp_m * 32 + la) * 64);
    int swa = (la >> 1) & 3;
    int acb = lane >> 4;                            // logical chunk base 0/1
    int rb = (lane & 7) | ((lane >> 4) << 3);
    uint32_t b_row = (uint32_t)((warp_n * 32 + rb) * 64);
    int swb = (rb >> 1) & 3;
    int bcb = (lane >> 3) & 1;

    g_load_stage(0, 0, sbase, tid, m0, n0, d_ahi, d_alo, whi);
    CP_COMMIT();
    g_load_stage(1, 1, sbase, tid, m0, n0, d_ahi, d_alo, whi);
    CP_COMMIT();
    g_load_stage(2, 2, sbase, tid, m0, n0, d_ahi, d_alo, whi);
    CP_COMMIT();

    for (int it = 0; it < KIT; ++it) {
        CP_WAIT2();
        __syncthreads();
        if (it + 3 < KIT)
            g_load_stage(it + 3, (it + 3) & 3, sbase, tid, m0, n0, d_ahi, d_alo, whi);
        CP_COMMIT();

        uint32_t sb = sbase + (it & 3) * STAGE_B;
        #pragma unroll
        for (int kk = 0; kk < 2; kk++) {
            uint32_t ah[4], al[4], bh[2][4];
            int pa = (acb | (kk << 1)) ^ swa;
            int pb = (bcb | (kk << 1)) ^ swb;
            // A: one 32-row warp tile = mt handled via two 16-row ldsm? rows 0..31
            // warp covers rows warp_m*32..+31; ldsm x4 covers 16 rows; need mt 0/1
            uint32_t ad0 = sb + a_row + (uint32_t)(pa * 16);
            uint32_t ad1 = ad0 + 16 * 64;
            LDSM4(ah, ad0);
            LDSM4(al, ad0 + ARR_A);
            #pragma unroll
            for (int p = 0; p < 2; p++) {
                uint32_t bd = sb + 2 * ARR_A + b_row + (uint32_t)(p * 1024 + pb * 16);
                LDSM4(bh[p], bd);
            }
            #pragma unroll
            for (int nt = 0; nt < 4; nt++) {
                int p = nt >> 1, q = (nt & 1) * 2;
                MMA16816(acc[0][nt], ah, bh[p][q], bh[p][q + 1]);
                MMA16816(acc[0][nt], al, bh[p][q], bh[p][q + 1]);
            }
            uint32_t ah2[4], al2[4];
            LDSM4(ah2, ad1);
            LDSM4(al2, ad1 + ARR_A);
            #pragma unroll
            for (int nt = 0; nt < 4; nt++) {
                int p = nt >> 1, q = (nt & 1) * 2;
                MMA16816(acc[1][nt], ah2, bh[p][q], bh[p][q + 1]);
                MMA16816(acc[1][nt], al2, bh[p][q], bh[p][q + 1]);
            }
        }
        __syncthreads();
    }

    // epilogue: c-frag (row=t/4, col=2*(t%4))
    int mrow = m0 + warp_m * 32 + (lane >> 2);
    int ncol = n0 + warp_n * 32 + (lane & 3) * 2;
    #pragma unroll
    for (int mt = 0; mt < 2; mt++)
        #pragma unroll
        for (int nt = 0; nt < 4; nt++) {
            int r1 = mrow + mt * 16, r2 = r1 + 8;
            int c = ncol + nt * 8;
            if (r1 < NN) {
                float2 v = make_float2(acc[mt][nt][0], acc[mt][nt][1]);
                *reinterpret_cast<float2*>(&d_t[((size_t)r1 << 10) + c]) = v;
            }
            if (r2 < NN) {
                float2 v = make_float2(acc[mt][nt][2], acc[mt][nt][3]);
                *reinterpret_cast<float2*>(&d_t[((size_t)r2 << 10) + c]) = v;
            }
        }
}

// ---- pooling + FC head ----
__global__ void k_bstart(const int* __restrict__ batch) {
    int g = threadIdx.x;
    if (g > NG) return;
    int lo = 0, hi = NN;
    while (lo < hi) { int m = (lo + hi) >> 1; if (batch[m] < g) lo = m + 1; else hi = m; }
    d_bstart[g] = lo;
}
__global__ void k_pool() {
    int g = blockIdx.x, col = blockIdx.y * 128 + threadIdx.x;
    int b = d_bstart[g], e = d_bstart[g + 1];
    float s = 0.f;
    for (int n = b; n < e; n++) s += d_h[(size_t)n * HD + col];
    d_pool[g * HD + col] = s / fmaxf((float)(e - b), 1.0f);
}
__global__ void k_fc1(const float* __restrict__ fw1, const float* __restrict__ fb1) {
    int g = blockIdx.x, j = threadIdx.x;
    float acc = fb1[j];
    for (int k = 0; k < HD; k++) acc += d_pool[g * HD + k] * fw1[k * 256 + j];
    d_o1[g * 256 + j] = acc;
}
__global__ void k_fc2(const float* __restrict__ fw2, const float* __restrict__ fb2,
                      float* __restrict__ out) {
    int g = blockIdx.x, j = threadIdx.x;   // 256 threads
    float v = d_o1[g * 256 + j] * fw2[j];
    v = warp_sum(v);
    __shared__ float sh[8];
    if ((j & 31) == 0) sh[j >> 5] = v;
    __syncthreads();
    if (j == 0) {
        float a = 0.f;
        for (int w = 0; w < 8; w++) a += sh[w];
        out[g] = a + fb2[0];
    }
}

extern "C" void kernel_launch(void* const* d_in, const int* in_sizes, int n_in,
                              void* d_out, int out_size) {
    const float* x    = (const float*)d_in[0];
    const int*   ei   = (const int*)  d_in[1];
    const int*   bat  = (const int*)  d_in[2];
    const float* W1   = (const float*)d_in[3];
    const float* b1   = (const float*)d_in[4];
    const float* W2   = (const float*)d_in[5];
    const float* b2   = (const float*)d_in[6];
    const float* W3   = (const float*)d_in[7];
    const float* b3   = (const float*)d_in[8];
    const float* g1   = (const float*)d_in[9];
    const float* be1  = (const float*)d_in[10];
    const float* g2   = (const float*)d_in[11];
    const float* be2  = (const float*)d_in[12];
    const float* g3   = (const float*)d_in[13];
    const float* be3  = (const float*)d_in[14];
    const float* fw1  = (const float*)d_in[15];
    const float* fb1  = (const float*)d_in[16];
    const float* fw2  = (const float*)d_in[17];
    const float* fb2  = (const float*)d_in[18];
    float* out = (float*)d_out;

    cudaFuncSetAttribute(k_gemm, cudaFuncAttributeMaxDynamicSharedMemorySize, GEMM_SMEM);

    k_init<<<(NN + 255) / 256, 256>>>();
    k_count<<<(NE + 255) / 256, 256>>>(ei);
    k_dinv<<<(NN + 255) / 256, 256>>>();
    k_scan<<<1, 1024>>>();
    k_fill<<<(NE + 255) / 256, 256>>>(ei);
    k_s<<<(NN + 255) / 256, 256>>>(x);
    k_t1<<<(NN * HD + 255) / 256, 256>>>(W1);
    dim3 wg(HD / 32, HD / 32), wb(32, 8);
    k_wsplit<<<wg, wb>>>(W2, 2);
    k_wsplit<<<wg, wb>>>(W3, 3);

    dim3 gg((NN + BM - 1) / BM, HD / BN);

    k_ln_act<<<NN, 256>>>(b1, g1, be1);
    k_agg<<<NN, 256>>>();
    k_gemm<<<gg, 256, GEMM_SMEM>>>(2);
    k_ln_act<<<NN, 256>>>(b2, g2, be2);
    k_agg<<<NN, 256>>>();
    k_gemm<<<gg, 256, GEMM_SMEM>>>(3);
    k_ln_act<<<NN, 256>>>(b3, g3, be3);

    k_bstart<<<1, 32>>>(bat);
    k_pool<<<dim3(NG, HD / 128), 128>>>();
    k_fc1<<<NG, 256>>>(fw1, fb1);
    k_fc2<<<NG, 256>>>(fw2, fb2, out);
}

// round 11
// speedup vs baseline: 1.1596x; 1.0934x over previous
#include <cuda_runtime.h>
#include <cuda_fp16.h>
#include <cstdint>

#define NN 20000
#define NE 160000
#define HD 1024
#define NG 16
#define EPSV 1e-5f
#define SLOPE 0.01f

// ---- device scratch (no allocs allowed) ----
__device__ float   d_h  [(size_t)NN * HD];
__device__ float   d_t  [(size_t)NN * HD];
__device__ __half  d_ahi[(size_t)NN * HD];
__device__ __half  d_alo[(size_t)NN * HD];
__device__ __half  d_w2hi[HD * HD], d_w2lo[HD * HD];
__device__ __half  d_w3hi[HD * HD], d_w3lo[HD * HD];
__device__ int     d_cnt[NN], d_offs[NN], d_deg[NN], d_cur[NN], d_csr[NE];
__device__ int     d_total;
__device__ float   d_dinv[NN], d_s[NN];
__device__ int     d_bstart[NG + 1];
__device__ float   d_pool[NG * HD];
__device__ float   d_o1[NG * 256];

__device__ __forceinline__ float warp_sum(float v) {
    #pragma unroll
    for (int o = 16; o; o >>= 1) v += __shfl_xor_sync(0xffffffffu, v, o);
    return v;
}

// ---- graph preprocessing ----
__global__ void k_init() {
    int i = blockIdx.x * blockDim.x + threadIdx.x;
    if (i < NN) d_cnt[i] = 0;
    if (i == 0) d_total = 0;
}
__global__ void k_count(const int* __restrict__ ei) {
    int e = blockIdx.x * blockDim.x + threadIdx.x;
    if (e < NE) atomicAdd(&d_cnt[ei[NE + e]], 1);
}
// slot allocation via global cursor — CSR order is irrelevant (commutative sums)
__global__ void k_offs() {
    int n = blockIdx.x * blockDim.x + threadIdx.x;
    if (n >= NN) return;
    int c = d_cnt[n];
    int st = atomicAdd(&d_total, c);
    d_offs[n] = st;
    d_cur[n] = st;
    d_deg[n] = c;
    d_dinv[n] = rsqrtf((float)(c + 1));
}
__global__ void k_fill(const int* __restrict__ ei) {
    int e = blockIdx.x * blockDim.x + threadIdx.x;
    if (e < NE) d_csr[atomicAdd(&d_cur[ei[NE + e]], 1)] = ei[e];
}

// layer-1 scalar aggregation (IN=1 makes conv1 rank-1)
__global__ void k_s(const float* __restrict__ x) {
    int n = blockIdx.x * blockDim.x + threadIdx.x;
    if (n >= NN) return;
    float dv = d_dinv[n];
    float acc = dv * x[n];
    int b = d_offs[n], e = b + d_deg[n];
    for (int j = b; j < e; j++) { int s = d_csr[j]; acc += d_dinv[s] * x[s]; }
    d_s[n] = dv * acc;
}

// W^T + fp16 hi/lo split: out[n*HD+k] = split(W[k*HD+n])
__global__ void k_wsplit(const float* __restrict__ W, int which) {
    __half* hi = (which == 2) ? d_w2hi : d_w3hi;
    __half* lo = (which == 2) ? d_w2lo : d_w3lo;
    __shared__ float tile[32][33];
    int bx = blockIdx.x * 32, by = blockIdx.y * 32;
    int tx = threadIdx.x, ty = threadIdx.y;
    for (int r = ty; r < 32; r += 8)
        tile[r][tx] = W[(size_t)(by + r) * HD + bx + tx];
    __syncthreads();
    for (int r = ty; r < 32; r += 8) {
        float w = tile[tx][r];
        __half h = __float2half_rn(w);
        size_t o = (size_t)(bx + r) * HD + by + tx;
        hi[o] = h;
        lo[o] = __float2half_rn(w - __half2float(h));
    }
}

// fused layer-1: h = act(LN(s*W1+b1)*g1 + be1)  (k_ln_act clone, d_t read replaced)
__global__ void k_ln1f(const float* __restrict__ W1, const float* __restrict__ b1,
                       const float* __restrict__ gam, const float* __restrict__ bet) {
    int n = blockIdx.x, tid = threadIdx.x;
    int wid = tid >> 5, lane = tid & 31;
    float sc = d_s[n];
    float v[4], s = 0.f, sq = 0.f;
    #pragma unroll
    for (int k = 0; k < 4; k++) {
        int c = tid + k * 256;
        float xv = sc * W1[c] + b1[c];
        v[k] = xv; s += xv; sq += xv * xv;
    }
    s = warp_sum(s); sq = warp_sum(sq);
    __shared__ float shs[8], shq[8];
    if (lane == 0) { shs[wid] = s; shq[wid] = sq; }
    __syncthreads();
    if (wid == 0) {
        float a = (lane < 8) ? shs[lane] : 0.f;
        float b = (lane < 8) ? shq[lane] : 0.f;
        a = warp_sum(a); b = warp_sum(b);
        if (lane == 0) { shs[0] = a; shq[0] = b; }
    }
    __syncthreads();
    float mu = shs[0] * (1.f / HD);
    float var = shq[0] * (1.f / HD) - mu * mu;
    float r = rsqrtf(var + EPSV);
    #pragma unroll
    for (int k = 0; k < 4; k++) {
        int c = tid + k * 256;
        float y = (v[k] - mu) * r * gam[c] + bet[c];
        d_h[(size_t)n * HD + c] = (y >= 0.f) ? y : SLOPE * y;
    }
}

// LN + LeakyReLU (layers 2/3): h = act(LN(t + bias)*g + be)
__global__ void k_ln_act(const float* __restrict__ bias,
                         const float* __restrict__ gam,
                         const float* __restrict__ bet) {
    int n = blockIdx.x, tid = threadIdx.x;
    int wid = tid >> 5, lane = tid & 31;
    float v[4], s = 0.f, sq = 0.f;
    #pragma unroll
    for (int k = 0; k < 4; k++) {
        int c = tid + k * 256;
        float xv = d_t[(size_t)n * HD + c] + bias[c];
        v[k] = xv; s += xv; sq += xv * xv;
    }
    s = warp_sum(s); sq = warp_sum(sq);
    __shared__ float shs[8], shq[8];
    if (lane == 0) { shs[wid] = s; shq[wid] = sq; }
    __syncthreads();
    if (wid == 0) {
        float a = (lane < 8) ? shs[lane] : 0.f;
        float b = (lane < 8) ? shq[lane] : 0.f;
        a = warp_sum(a); b = warp_sum(b);
        if (lane == 0) { shs[0] = a; shq[0] = b; }
    }
    __syncthreads();
    float mu = shs[0] * (1.f / HD);
    float var = shq[0] * (1.f / HD) - mu * mu;
    float r = rsqrtf(var + EPSV);
    #pragma unroll
    for (int k = 0; k < 4; k++) {
        int c = tid + k * 256;
        float y = (v[k] - mu) * r * gam[c] + bet[c];
        d_h[(size_t)n * HD + c] = (y >= 0.f) ? y : SLOPE * y;
    }
}

// aggregation of d_h -> fp16 hi/lo (one block per node)
__global__ void k_agg() {
    int dd = blockIdx.x, tid = threadIdx.x;
    float dv = d_dinv[dd];
    float acc[4];
    #pragma unroll
    for (int k = 0; k < 4; k++)
        acc[k] = dv * d_h[(size_t)dd * HD + tid + k * 256];
    int b = d_offs[dd], e = b + d_deg[dd];
    for (int j = b; j < e; j++) {
        int s = d_csr[j];
        float w = d_dinv[s];
        const float* hr = &d_h[(size_t)s * HD];
        #pragma unroll
        for (int k = 0; k < 4; k++) acc[k] += w * hr[tid + k * 256];
    }
    #pragma unroll
    for (int k = 0; k < 4; k++) {
        int c = tid + k * 256;
        float o = dv * acc[k];
        __half h = __float2half_rn(o);
        d_ahi[(size_t)dd * HD + c] = h;
        d_alo[(size_t)dd * HD + c] = __float2half_rn(o - __half2float(h));
    }
}

// ---- mma.sync GEMM: d_t = Agg @ W  (2 products: (a_hi+a_lo)*b_hi) ----
// 256-thread CTA, BM=64 x BN=128, XOR-swizzled smem, 4 stages, 16KB/stage
#define BM 64
#define BN 128
#define BK 32
#define KIT (HD / BK)          // 32
#define STAGES 4
#define ARR_A (BM * 64)        // 4096 bytes per A array
#define ARR_BB (BN * 64)       // 8192 bytes for B array
#define STAGE_B (2 * ARR_A + ARR_BB)   // 16384 bytes per stage
#define GEMM_SMEM (STAGES * STAGE_B)   // 65536

__device__ __forceinline__ void cp16(uint32_t saddr, const void* g, int sz) {
    asm volatile("cp.async.cg.shared.global [%0], [%1], 16, %2;"
                 :: "r"(saddr), "l"(g), "r"(sz));
}
#define CP_COMMIT() asm volatile("cp.async.commit_group;" ::: "memory")
#define CP_WAIT2()  asm volatile("cp.async.wait_group 2;" ::: "memory")

#define LDSM4(r, addr)                                                          \
    asm volatile("ldmatrix.sync.aligned.m8n8.x4.shared.b16 {%0,%1,%2,%3}, [%4];"\
                 : "=r"((r)[0]), "=r"((r)[1]), "=r"((r)[2]), "=r"((r)[3])       \
                 : "r"(addr))

#define MMA16816(c, a, b0, b1)                                                  \
    asm volatile("mma.sync.aligned.m16n8k16.row.col.f32.f16.f16.f32 "           \
                 "{%0,%1,%2,%3}, {%4,%5,%6,%7}, {%8,%9}, {%0,%1,%2,%3};"        \
                 : "+f"((c)[0]), "+f"((c)[1]), "+f"((c)[2]), "+f"((c)[3])       \
                 : "r"((a)[0]), "r"((a)[1]), "r"((a)[2]), "r"((a)[3]),          \
                   "r"(b0), "r"(b1))

__device__ __forceinline__ void g_load_stage(
    int it, int s, uint32_t sbase, int tid, int m0, int n0,
    const __half* ahi, const __half* alo, const __half* bhi)
{
    int k0 = it * BK;
    uint32_t sb = sbase + s * STAGE_B;
    int row = tid >> 2, ch = tid & 3;
    int p = ch ^ ((row >> 1) & 3);
    uint32_t so = (uint32_t)(row * 64 + p * 16);
    int gr = m0 + row;
    int asz = (gr < NN) ? 16 : 0;
    size_t aoff = ((size_t)((gr < NN) ? gr : 0) << 10) + k0 + ch * 8;
    cp16(sb + 0 * ARR_A + so, ahi + aoff, asz);
    cp16(sb + 1 * ARR_A + so, alo + aoff, asz);
    size_t boff = ((size_t)(n0 + row) << 10) + k0 + ch * 8;
    cp16(sb + 2 * ARR_A + so, bhi + boff, 16);
    int row2 = row + 64;
    int p2 = ch ^ ((row2 >> 1) & 3);
    uint32_t so2 = (uint32_t)(row2 * 64 + p2 * 16);
    size_t boff2 = ((size_t)(n0 + row2) << 10) + k0 + ch * 8;
    cp16(sb + 2 * ARR_A + so2, bhi + boff2, 16);
}

__global__ void __launch_bounds__(256) k_gemm(int which) {
    extern __shared__ char smem[];
    const __half* whi = (which == 2) ? d_w2hi : d_w3hi;
    uint32_t sbase = (uint32_t)__cvta_generic_to_shared(smem);
    int tid = threadIdx.x;
    int lane = tid & 31, wid = tid >> 5;
    int warp_m = wid & 1, warp_n = wid >> 1;
    int m0 = blockIdx.x * BM, n0 = blockIdx.y * BN;

    float acc[2][4][4];
    #pragma unroll
    for (int mt = 0; mt < 2; mt++)
        #pragma unroll
        for (int nt = 0; nt < 4; nt++)
            #pragma unroll
            for (int q = 0; q < 4; q++) acc[mt][nt][q] = 0.f;

    int la = lane & 15;
    uint32_t a_row = (uint32_t)((warp_m * 32 + la) * 64);
    int swa = (la >> 1) & 3;
    int acb = lane >> 4;
    int rb = (lane & 7) | ((lane >> 4) << 3);
    uint32_t b_row = (uint32_t)((warp_n * 32 + rb) * 64);
    int swb = (rb >> 1) & 3;
    int bcb = (lane >> 3) & 1;

    g_load_stage(0, 0, sbase, tid, m0, n0, d_ahi, d_alo, whi);
    CP_COMMIT();
    g_load_stage(1, 1, sbase, tid, m0, n0, d_ahi, d_alo, whi);
    CP_COMMIT();
    g_load_stage(2, 2, sbase, tid, m0, n0, d_ahi, d_alo, whi);
    CP_COMMIT();

    for (int it = 0; it < KIT; ++it) {
        CP_WAIT2();
        __syncthreads();
        if (it + 3 < KIT)
            g_load_stage(it + 3, (it + 3) & 3, sbase, tid, m0, n0, d_ahi, d_alo, whi);
        CP_COMMIT();

        uint32_t sb = sbase + (it & 3) * STAGE_B;
        #pragma unroll
        for (int kk = 0; kk < 2; kk++) {
            uint32_t ah[4], al[4], bh[2][4];
            int pa = (acb | (kk << 1)) ^ swa;
            int pb = (bcb | (kk << 1)) ^ swb;
            uint32_t ad0 = sb + a_row + (uint32_t)(pa * 16);
            uint32_t ad1 = ad0 + 16 * 64;
            LDSM4(ah, ad0);
            LDSM4(al, ad0 + ARR_A);
            #pragma unroll
            for (int p = 0; p < 2; p++) {
                uint32_t bd = sb + 2 * ARR_A + b_row + (uint32_t)(p * 1024 + pb * 16);
                LDSM4(bh[p], bd);
            }
            #pragma unroll
            for (int nt = 0; nt < 4; nt++) {
                int p = nt >> 1, q = (nt & 1) * 2;
                MMA16816(acc[0][nt], ah, bh[p][q], bh[p][q + 1]);
                MMA16816(acc[0][nt], al, bh[p][q], bh[p][q + 1]);
            }
            uint32_t ah2[4], al2[4];
            LDSM4(ah2, ad1);
            LDSM4(al2, ad1 + ARR_A);
            #pragma unroll
            for (int nt = 0; nt < 4; nt++) {
                int p = nt >> 1, q = (nt & 1) * 2;
                MMA16816(acc[1][nt], ah2, bh[p][q], bh[p][q + 1]);
                MMA16816(acc[1][nt], al2, bh[p][q], bh[p][q + 1]);
            }
        }
        __syncthreads();
    }

    int mrow = m0 + warp_m * 32 + (lane >> 2);
    int ncol = n0 + warp_n * 32 + (lane & 3) * 2;
    #pragma unroll
    for (int mt = 0; mt < 2; mt++)
        #pragma unroll
        for (int nt = 0; nt < 4; nt++) {
            int r1 = mrow + mt * 16, r2 = r1 + 8;
            int c = ncol + nt * 8;
            if (r1 < NN) {
                float2 v = make_float2(acc[mt][nt][0], acc[mt][nt][1]);
                *reinterpret_cast<float2*>(&d_t[((size_t)r1 << 10) + c]) = v;
            }
            if (r2 < NN) {
                float2 v = make_float2(acc[mt][nt][2], acc[mt][nt][3]);
                *reinterpret_cast<float2*>(&d_t[((size_t)r2 << 10) + c]) = v;
            }
        }
}

// ---- pooling + FC head ----
__global__ void k_bstart(const int* __restrict__ batch) {
    int g = threadIdx.x;
    if (g > NG) return;
    int lo = 0, hi = NN;
    while (lo < hi) { int m = (lo + hi) >> 1; if (batch[m] < g) lo = m + 1; else hi = m; }
    d_bstart[g] = lo;
}
__global__ void k_pool() {
    int g = blockIdx.x, col = blockIdx.y * 128 + threadIdx.x;
    int b = d_bstart[g], e = d_bstart[g + 1];
    float s = 0.f;
    for (int n = b; n < e; n++) s += d_h[(size_t)n * HD + col];
    d_pool[g * HD + col] = s / fmaxf((float)(e - b), 1.0f);
}
__global__ void k_fc1(const float* __restrict__ fw1, const float* __restrict__ fb1) {
    int g = blockIdx.x, j = threadIdx.x;
    float acc = fb1[j];
    for (int k = 0; k < HD; k++) acc += d_pool[g * HD + k] * fw1[k * 256 + j];
    d_o1[g * 256 + j] = acc;
}
__global__ void k_fc2(const float* __restrict__ fw2, const float* __restrict__ fb2,
                      float* __restrict__ out) {
    int g = blockIdx.x, j = threadIdx.x;
    float v = d_o1[g * 256 + j] * fw2[j];
    v = warp_sum(v);
    __shared__ float sh[8];
    if ((j & 31) == 0) sh[j >> 5] = v;
    __syncthreads();
    if (j == 0) {
        float a = 0.f;
        for (int w = 0; w < 8; w++) a += sh[w];
        out[g] = a + fb2[0];
    }
}

extern "C" void kernel_launch(void* const* d_in, const int* in_sizes, int n_in,
                              void* d_out, int out_size) {
    const float* x    = (const float*)d_in[0];
    const int*   ei   = (const int*)  d_in[1];
    const int*   bat  = (const int*)  d_in[2];
    const float* W1   = (const float*)d_in[3];
    const float* b1   = (const float*)d_in[4];
    const float* W2   = (const float*)d_in[5];
    const float* b2   = (const float*)d_in[6];
    const float* W3   = (const float*)d_in[7];
    const float* b3   = (const float*)d_in[8];
    const float* g1   = (const float*)d_in[9];
    const float* be1  = (const float*)d_in[10];
    const float* g2   = (const float*)d_in[11];
    const float* be2  = (const float*)d_in[12];
    const float* g3   = (const float*)d_in[13];
    const float* be3  = (const float*)d_in[14];
    const float* fw1  = (const float*)d_in[15];
    const float* fb1  = (const float*)d_in[16];
    const float* fw2  = (const float*)d_in[17];
    const float* fb2  = (const float*)d_in[18];
    float* out = (float*)d_out;

    cudaFuncSetAttribute(k_gemm, cudaFuncAttributeMaxDynamicSharedMemorySize, GEMM_SMEM);

    k_init<<<(NN + 255) / 256, 256>>>();
    k_count<<<(NE + 255) / 256, 256>>>(ei);
    k_offs<<<(NN + 255) / 256, 256>>>();
    k_fill<<<(NE + 255) / 256, 256>>>(ei);
    k_s<<<(NN + 255) / 256, 256>>>(x);
    dim3 wg(HD / 32, HD / 32), wb(32, 8);
    k_wsplit<<<wg, wb>>>(W2, 2);
    k_wsplit<<<wg, wb>>>(W3, 3);

    dim3 gg((NN + BM - 1) / BM, HD / BN);

    k_ln1f<<<NN, 256>>>(W1, b1, g1, be1);
    k_agg<<<NN, 256>>>();
    k_gemm<<<gg, 256, GEMM_SMEM>>>(2);
    k_ln_act<<<NN, 256>>>(b2, g2, be2);
    k_agg<<<NN, 256>>>();
    k_gemm<<<gg, 256, GEMM_SMEM>>>(3);
    k_ln_act<<<NN, 256>>>(b3, g3, be3);

    k_bstart<<<1, 32>>>(bat);
    k_pool<<<dim3(NG, HD / 128), 128>>>();
    k_fc1<<<NG, 256>>>(fw1, fb1);
    k_fc2<<<NG, 256>>>(fw2, fb2, out);
}

// round 12
// speedup vs baseline: 1.2181x; 1.0504x over previous
#include <cuda_runtime.h>
#include <cuda_fp16.h>
#include <cstdint>

#define NN 20000
#define NE 160000
#define HD 1024
#define NG 16
#define EPSV 1e-5f
#define SLOPE 0.01f

// ---- device scratch (no allocs allowed) ----
__device__ float   d_h  [(size_t)NN * HD];
__device__ float   d_t  [(size_t)NN * HD];
__device__ __half  d_ahi[(size_t)NN * HD];
__device__ __half  d_alo[(size_t)NN * HD];
__device__ __half  d_w2hi[HD * HD], d_w2lo[HD * HD];
__device__ __half  d_w3hi[HD * HD], d_w3lo[HD * HD];
__device__ int     d_cnt[NN], d_offs[NN], d_deg[NN], d_cur[NN], d_csr[NE];
__device__ int     d_total;
__device__ float   d_dinv[NN], d_s[NN];
__device__ int     d_bstart[NG + 1];
__device__ float   d_pool[NG * HD];
__device__ float   d_o1[NG * 256];

__device__ __forceinline__ float warp_sum(float v) {
    #pragma unroll
    for (int o = 16; o; o >>= 1) v += __shfl_xor_sync(0xffffffffu, v, o);
    return v;
}

// ---- graph preprocessing ----
__global__ void k_init() {
    int i = blockIdx.x * blockDim.x + threadIdx.x;
    if (i < NN) d_cnt[i] = 0;
    if (i == 0) d_total = 0;
}
__global__ void k_count(const int* __restrict__ ei) {
    int e = blockIdx.x * blockDim.x + threadIdx.x;
    if (e < NE) atomicAdd(&d_cnt[ei[NE + e]], 1);
}
// slot allocation via global cursor — CSR order is irrelevant (commutative sums)
__global__ void k_offs() {
    int n = blockIdx.x * blockDim.x + threadIdx.x;
    if (n >= NN) return;
    int c = d_cnt[n];
    int st = atomicAdd(&d_total, c);
    d_offs[n] = st;
    d_cur[n] = st;
    d_deg[n] = c;
    d_dinv[n] = rsqrtf((float)(c + 1));
}
__global__ void k_fill(const int* __restrict__ ei) {
    int e = blockIdx.x * blockDim.x + threadIdx.x;
    if (e < NE) d_csr[atomicAdd(&d_cur[ei[NE + e]], 1)] = ei[e];
}

// layer-1 scalar aggregation (IN=1 makes conv1 rank-1)
__global__ void k_s(const float* __restrict__ x) {
    int n = blockIdx.x * blockDim.x + threadIdx.x;
    if (n >= NN) return;
    float dv = d_dinv[n];
    float acc = dv * x[n];
    int b = d_offs[n], e = b + d_deg[n];
    for (int j = b; j < e; j++) { int s = d_csr[j]; acc += d_dinv[s] * x[s]; }
    d_s[n] = dv * acc;
}

// W^T + fp16 hi/lo split: out[n*HD+k] = split(W[k*HD+n])
__global__ void k_wsplit(const float* __restrict__ W, int which) {
    __half* hi = (which == 2) ? d_w2hi : d_w3hi;
    __half* lo = (which == 2) ? d_w2lo : d_w3lo;
    __shared__ float tile[32][33];
    int bx = blockIdx.x * 32, by = blockIdx.y * 32;
    int tx = threadIdx.x, ty = threadIdx.y;
    for (int r = ty; r < 32; r += 8)
        tile[r][tx] = W[(size_t)(by + r) * HD + bx + tx];
    __syncthreads();
    for (int r = ty; r < 32; r += 8) {
        float w = tile[tx][r];
        __half h = __float2half_rn(w);
        size_t o = (size_t)(bx + r) * HD + by + tx;
        hi[o] = h;
        lo[o] = __float2half_rn(w - __half2float(h));
    }
}

// fused layer-1: h = act(LN(s*W1+b1)*g1 + be1), float4 vectorized
__global__ void k_ln1f(const float* __restrict__ W1, const float* __restrict__ b1,
                       const float* __restrict__ gam, const float* __restrict__ bet) {
    int n = blockIdx.x, tid = threadIdx.x;
    int wid = tid >> 5, lane = tid & 31;
    float sc = d_s[n];
    float4 w4 = reinterpret_cast<const float4*>(W1)[tid];
    float4 bb = reinterpret_cast<const float4*>(b1)[tid];
    float4 v;
    v.x = sc * w4.x + bb.x; v.y = sc * w4.y + bb.y;
    v.z = sc * w4.z + bb.z; v.w = sc * w4.w + bb.w;
    float s = v.x + v.y + v.z + v.w;
    float sq = v.x * v.x + v.y * v.y + v.z * v.z + v.w * v.w;
    s = warp_sum(s); sq = warp_sum(sq);
    __shared__ float shs[8], shq[8];
    if (lane == 0) { shs[wid] = s; shq[wid] = sq; }
    __syncthreads();
    if (wid == 0) {
        float a = (lane < 8) ? shs[lane] : 0.f;
        float b = (lane < 8) ? shq[lane] : 0.f;
        a = warp_sum(a); b = warp_sum(b);
        if (lane == 0) { shs[0] = a; shq[0] = b; }
    }
    __syncthreads();
    float mu = shs[0] * (1.f / HD);
    float var = shq[0] * (1.f / HD) - mu * mu;
    float r = rsqrtf(var + EPSV);
    float4 g4 = reinterpret_cast<const float4*>(gam)[tid];
    float4 e4 = reinterpret_cast<const float4*>(bet)[tid];
    float4 y;
    y.x = (v.x - mu) * r * g4.x + e4.x;
    y.y = (v.y - mu) * r * g4.y + e4.y;
    y.z = (v.z - mu) * r * g4.z + e4.z;
    y.w = (v.w - mu) * r * g4.w + e4.w;
    y.x = (y.x >= 0.f) ? y.x : SLOPE * y.x;
    y.y = (y.y >= 0.f) ? y.y : SLOPE * y.y;
    y.z = (y.z >= 0.f) ? y.z : SLOPE * y.z;
    y.w = (y.w >= 0.f) ? y.w : SLOPE * y.w;
    reinterpret_cast<float4*>(d_h)[(size_t)n * 256 + tid] = y;
}

// LN + LeakyReLU (layers 2/3), float4 vectorized
__global__ void k_ln_act(const float* __restrict__ bias,
                         const float* __restrict__ gam,
                         const float* __restrict__ bet) {
    int n = blockIdx.x, tid = threadIdx.x;
    int wid = tid >> 5, lane = tid & 31;
    float4 t4 = reinterpret_cast<const float4*>(d_t)[(size_t)n * 256 + tid];
    float4 bb = reinterpret_cast<const float4*>(bias)[tid];
    float4 v;
    v.x = t4.x + bb.x; v.y = t4.y + bb.y; v.z = t4.z + bb.z; v.w = t4.w + bb.w;
    float s = v.x + v.y + v.z + v.w;
    float sq = v.x * v.x + v.y * v.y + v.z * v.z + v.w * v.w;
    s = warp_sum(s); sq = warp_sum(sq);
    __shared__ float shs[8], shq[8];
    if (lane == 0) { shs[wid] = s; shq[wid] = sq; }
    __syncthreads();
    if (wid == 0) {
        float a = (lane < 8) ? shs[lane] : 0.f;
        float b = (lane < 8) ? shq[lane] : 0.f;
        a = warp_sum(a); b = warp_sum(b);
        if (lane == 0) { shs[0] = a; shq[0] = b; }
    }
    __syncthreads();
    float mu = shs[0] * (1.f / HD);
    float var = shq[0] * (1.f / HD) - mu * mu;
    float r = rsqrtf(var + EPSV);
    float4 g4 = reinterpret_cast<const float4*>(gam)[tid];
    float4 e4 = reinterpret_cast<const float4*>(bet)[tid];
    float4 y;
    y.x = (v.x - mu) * r * g4.x + e4.x;
    y.y = (v.y - mu) * r * g4.y + e4.y;
    y.z = (v.z - mu) * r * g4.z + e4.z;
    y.w = (v.w - mu) * r * g4.w + e4.w;
    y.x = (y.x >= 0.f) ? y.x : SLOPE * y.x;
    y.y = (y.y >= 0.f) ? y.y : SLOPE * y.y;
    y.z = (y.z >= 0.f) ? y.z : SLOPE * y.z;
    y.w = (y.w >= 0.f) ? y.w : SLOPE * y.w;
    reinterpret_cast<float4*>(d_h)[(size_t)n * 256 + tid] = y;
}

// aggregation of d_h -> fp16 hi/lo, float4 gather + half2 stores
__global__ void k_agg() {
    int dd = blockIdx.x, tid = threadIdx.x;
    float dv = d_dinv[dd];
    const float4* hb = reinterpret_cast<const float4*>(d_h);
    float4 a = hb[(size_t)dd * 256 + tid];
    float4 acc = make_float4(dv * a.x, dv * a.y, dv * a.z, dv * a.w);
    int b = d_offs[dd], e = b + d_deg[dd];
    for (int j = b; j < e; j++) {
        int s = d_csr[j];
        float w = d_dinv[s];
        float4 v = hb[(size_t)s * 256 + tid];
        acc.x += w * v.x; acc.y += w * v.y; acc.z += w * v.z; acc.w += w * v.w;
    }
    acc.x *= dv; acc.y *= dv; acc.z *= dv; acc.w *= dv;
    __half hx = __float2half_rn(acc.x), hy = __float2half_rn(acc.y);
    __half hz = __float2half_rn(acc.z), hw = __float2half_rn(acc.w);
    __half2* hi2 = reinterpret_cast<__half2*>(d_ahi) + (size_t)dd * 512 + tid * 2;
    __half2* lo2 = reinterpret_cast<__half2*>(d_alo) + (size_t)dd * 512 + tid * 2;
    hi2[0] = __halves2half2(hx, hy);
    hi2[1] = __halves2half2(hz, hw);
    lo2[0] = __halves2half2(__float2half_rn(acc.x - __half2float(hx)),
                            __float2half_rn(acc.y - __half2float(hy)));
    lo2[1] = __halves2half2(__float2half_rn(acc.z - __half2float(hz)),
                            __float2half_rn(acc.w - __half2float(hw)));
}

// ---- mma.sync GEMM: d_t = Agg @ W  (2 products: (a_hi+a_lo)*b_hi) ----
// 256-thread CTA, BM=64 x BN=128, XOR-swizzled smem, 4 stages, 16KB/stage
// grid = (N-tiles, M-tiles): co-resident CTAs share A rows -> L2 A reuse.
#define BM 64
#define BN 128
#define BK 32
#define KIT (HD / BK)          // 32
#define STAGES 4
#define ARR_A (BM * 64)        // 4096 bytes per A array
#define ARR_BB (BN * 64)       // 8192 bytes for B array
#define STAGE_B (2 * ARR_A + ARR_BB)   // 16384 bytes per stage
#define GEMM_SMEM (STAGES * STAGE_B)   // 65536

__device__ __forceinline__ void cp16(uint32_t saddr, const void* g, int sz) {
    asm volatile("cp.async.cg.shared.global [%0], [%1], 16, %2;"
                 :: "r"(saddr), "l"(g), "r"(sz));
}
#define CP_COMMIT() asm volatile("cp.async.commit_group;" ::: "memory")
#define CP_WAIT2()  asm volatile("cp.async.wait_group 2;" ::: "memory")

#define LDSM4(r, addr)                                                          \
    asm volatile("ldmatrix.sync.aligned.m8n8.x4.shared.b16 {%0,%1,%2,%3}, [%4];"\
                 : "=r"((r)[0]), "=r"((r)[1]), "=r"((r)[2]), "=r"((r)[3])       \
                 : "r"(addr))

#define MMA16816(c, a, b0, b1)                                                  \
    asm volatile("mma.sync.aligned.m16n8k16.row.col.f32.f16.f16.f32 "           \
                 "{%0,%1,%2,%3}, {%4,%5,%6,%7}, {%8,%9}, {%0,%1,%2,%3};"        \
                 : "+f"((c)[0]), "+f"((c)[1]), "+f"((c)[2]), "+f"((c)[3])       \
                 : "r"((a)[0]), "r"((a)[1]), "r"((a)[2]), "r"((a)[3]),          \
                   "r"(b0), "r"(b1))

__device__ __forceinline__ void g_load_stage(
    int it, int s, uint32_t sbase, int tid, int m0, int n0,
    const __half* ahi, const __half* alo, const __half* bhi)
{
    int k0 = it * BK;
    uint32_t sb = sbase + s * STAGE_B;
    int row = tid >> 2, ch = tid & 3;
    int p = ch ^ ((row >> 1) & 3);
    uint32_t so = (uint32_t)(row * 64 + p * 16);
    int gr = m0 + row;
    int asz = (gr < NN) ? 16 : 0;
    size_t aoff = ((size_t)((gr < NN) ? gr : 0) << 10) + k0 + ch * 8;
    cp16(sb + 0 * ARR_A + so, ahi + aoff, asz);
    cp16(sb + 1 * ARR_A + so, alo + aoff, asz);
    size_t boff = ((size_t)(n0 + row) << 10) + k0 + ch * 8;
    cp16(sb + 2 * ARR_A + so, bhi + boff, 16);
    int row2 = row + 64;
    int p2 = ch ^ ((row2 >> 1) & 3);
    uint32_t so2 = (uint32_t)(row2 * 64 + p2 * 16);
    size_t boff2 = ((size_t)(n0 + row2) << 10) + k0 + ch * 8;
    cp16(sb + 2 * ARR_A + so2, bhi + boff2, 16);
}

__global__ void __launch_bounds__(256) k_gemm(int which) {
    extern __shared__ char smem[];
    const __half* whi = (which == 2) ? d_w2hi : d_w3hi;
    uint32_t sbase = (uint32_t)__cvta_generic_to_shared(smem);
    int tid = threadIdx.x;
    int lane = tid & 31, wid = tid >> 5;
    int warp_m = wid & 1, warp_n = wid >> 1;
    int m0 = blockIdx.y * BM, n0 = blockIdx.x * BN;   // N fastest-varying

    float acc[2][4][4];
    #pragma unroll
    for (int mt = 0; mt < 2; mt++)
        #pragma unroll
        for (int nt = 0; nt < 4; nt++)
            #pragma unroll
            for (int q = 0; q < 4; q++) acc[mt][nt][q] = 0.f;

    int la = lane & 15;
    uint32_t a_row = (uint32_t)((warp_m * 32 + la) * 64);
    int swa = (la >> 1) & 3;
    int acb = lane >> 4;
    int rb = (lane & 7) | ((lane >> 4) << 3);
    uint32_t b_row = (uint32_t)((warp_n * 32 + rb) * 64);
    int swb = (rb >> 1) & 3;
    int bcb = (lane >> 3) & 1;

    g_load_stage(0, 0, sbase, tid, m0, n0, d_ahi, d_alo, whi);
    CP_COMMIT();
    g_load_stage(1, 1, sbase, tid, m0, n0, d_ahi, d_alo, whi);
    CP_COMMIT();
    g_load_stage(2, 2, sbase, tid, m0, n0, d_ahi, d_alo, whi);
    CP_COMMIT();

    for (int it = 0; it < KIT; ++it) {
        CP_WAIT2();
        __syncthreads();
        if (it + 3 < KIT)
            g_load_stage(it + 3, (it + 3) & 3, sbase, tid, m0, n0, d_ahi, d_alo, whi);
        CP_COMMIT();

        uint32_t sb = sbase + (it & 3) * STAGE_B;
        #pragma unroll
        for (int kk = 0; kk < 2; kk++) {
            uint32_t ah[4], al[4], bh[2][4];
            int pa = (acb | (kk << 1)) ^ swa;
            int pb = (bcb | (kk << 1)) ^ swb;
            uint32_t ad0 = sb + a_row + (uint32_t)(pa * 16);
            uint32_t ad1 = ad0 + 16 * 64;
            LDSM4(ah, ad0);
            LDSM4(al, ad0 + ARR_A);
            #pragma unroll
            for (int p = 0; p < 2; p++) {
                uint32_t bd = sb + 2 * ARR_A + b_row + (uint32_t)(p * 1024 + pb * 16);
                LDSM4(bh[p], bd);
            }
            #pragma unroll
            for (int nt = 0; nt < 4; nt++) {
                int p = nt >> 1, q = (nt & 1) * 2;
                MMA16816(acc[0][nt], ah, bh[p][q], bh[p][q + 1]);
                MMA16816(acc[0][nt], al, bh[p][q], bh[p][q + 1]);
            }
            uint32_t ah2[4], al2[4];
            LDSM4(ah2, ad1);
            LDSM4(al2, ad1 + ARR_A);
            #pragma unroll
            for (int nt = 0; nt < 4; nt++) {
                int p = nt >> 1, q = (nt & 1) * 2;
                MMA16816(acc[1][nt], ah2, bh[p][q], bh[p][q + 1]);
                MMA16816(acc[1][nt], al2, bh[p][q], bh[p][q + 1]);
            }
        }
        __syncthreads();
    }

    int mrow = m0 + warp_m * 32 + (lane >> 2);
    int ncol = n0 + warp_n * 32 + (lane & 3) * 2;
    #pragma unroll
    for (int mt = 0; mt < 2; mt++)
        #pragma unroll
        for (int nt = 0; nt < 4; nt++) {
            int r1 = mrow + mt * 16, r2 = r1 + 8;
            int c = ncol + nt * 8;
            if (r1 < NN) {
                float2 v = make_float2(acc[mt][nt][0], acc[mt][nt][1]);
                *reinterpret_cast<float2*>(&d_t[((size_t)r1 << 10) + c]) = v;
            }
            if (r2 < NN) {
                float2 v = make_float2(acc[mt][nt][2], acc[mt][nt][3]);
                *reinterpret_cast<float2*>(&d_t[((size_t)r2 << 10) + c]) = v;
            }
        }
}

// ---- pooling + FC head ----
__global__ void k_bstart(const int* __restrict__ batch) {
    int g = threadIdx.x;
    if (g > NG) return;
    int lo = 0, hi = NN;
    while (lo < hi) { int m = (lo + hi) >> 1; if (batch[m] < g) lo = m + 1; else hi = m; }
    d_bstart[g] = lo;
}
__global__ void k_pool() {
    int g = blockIdx.x, col = blockIdx.y * 128 + threadIdx.x;
    int b = d_bstart[g], e = d_bstart[g + 1];
    float s = 0.f;
    for (int n = b; n < e; n++) s += d_h[(size_t)n * HD + col];
    d_pool[g * HD + col] = s / fmaxf((float)(e - b), 1.0f);
}
__global__ void k_fc1(const float* __restrict__ fw1, const float* __restrict__ fb1) {
    int g = blockIdx.x, j = threadIdx.x;
    float acc = fb1[j];
    for (int k = 0; k < HD; k++) acc += d_pool[g * HD + k] * fw1[k * 256 + j];
    d_o1[g * 256 + j] = acc;
}
__global__ void k_fc2(const float* __restrict__ fw2, const float* __restrict__ fb2,
                      float* __restrict__ out) {
    int g = blockIdx.x, j = threadIdx.x;
    float v = d_o1[g * 256 + j] * fw2[j];
    v = warp_sum(v);
    __shared__ float sh[8];
    if ((j & 31) == 0) sh[j >> 5] = v;
    __syncthreads();
    if (j == 0) {
        float a = 0.f;
        for (int w = 0; w < 8; w++) a += sh[w];
        out[g] = a + fb2[0];
    }
}

extern "C" void kernel_launch(void* const* d_in, const int* in_sizes, int n_in,
                              void* d_out, int out_size) {
    const float* x    = (const float*)d_in[0];
    const int*   ei   = (const int*)  d_in[1];
    const int*   bat  = (const int*)  d_in[2];
    const float* W1   = (const float*)d_in[3];
    const float* b1   = (const float*)d_in[4];
    const float* W2   = (const float*)d_in[5];
    const float* b2   = (const float*)d_in[6];
    const float* W3   = (const float*)d_in[7];
    const float* b3   = (const float*)d_in[8];
    const float* g1   = (const float*)d_in[9];
    const float* be1  = (const float*)d_in[10];
    const float* g2   = (const float*)d_in[11];
    const float* be2  = (const float*)d_in[12];
    const float* g3   = (const float*)d_in[13];
    const float* be3  = (const float*)d_in[14];
    const float* fw1  = (const float*)d_in[15];
    const float* fb1  = (const float*)d_in[16];
    const float* fw2  = (const float*)d_in[17];
    const float* fb2  = (const float*)d_in[18];
    float* out = (float*)d_out;

    cudaFuncSetAttribute(k_gemm, cudaFuncAttributeMaxDynamicSharedMemorySize, GEMM_SMEM);

    k_init<<<(NN + 255) / 256, 256>>>();
    k_count<<<(NE + 255) / 256, 256>>>(ei);
    k_offs<<<(NN + 255) / 256, 256>>>();
    k_fill<<<(NE + 255) / 256, 256>>>(ei);
    k_s<<<(NN + 255) / 256, 256>>>(x);
    dim3 wg(HD / 32, HD / 32), wb(32, 8);
    k_wsplit<<<wg, wb>>>(W2, 2);
    k_wsplit<<<wg, wb>>>(W3, 3);

    dim3 gg(HD / BN, (NN + BM - 1) / BM);   // N fastest -> A-tile L2 reuse

    k_ln1f<<<NN, 256>>>(W1, b1, g1, be1);
    k_agg<<<NN, 256>>>();
    k_gemm<<<gg, 256, GEMM_SMEM>>>(2);
    k_ln_act<<<NN, 256>>>(b2, g2, be2);
    k_agg<<<NN, 256>>>();
    k_gemm<<<gg, 256, GEMM_SMEM>>>(3);
    k_ln_act<<<NN, 256>>>(b3, g3, be3);

    k_bstart<<<1, 32>>>(bat);
    k_pool<<<dim3(NG, HD / 128), 128>>>();
    k_fc1<<<NG, 256>>>(fw1, fb1);
    k_fc2<<<NG, 256>>>(fw2, fb2, out);
}

// round 13
// speedup vs baseline: 1.2266x; 1.0070x over previous
#include <cuda_runtime.h>
#include <cuda_fp16.h>
#include <cstdint>

#define NN 20000
#define NE 160000
#define HD 1024
#define NG 16
#define EPSV 1e-5f
#define SLOPE 0.01f

// ---- device scratch (no allocs allowed) ----
__device__ float   d_h  [(size_t)NN * HD];
__device__ float   d_t  [(size_t)NN * HD];
__device__ __half  d_ahi[(size_t)NN * HD];
__device__ __half  d_alo[(size_t)NN * HD];
__device__ __half  d_w2hi[HD * HD], d_w2lo[HD * HD];
__device__ __half  d_w3hi[HD * HD], d_w3lo[HD * HD];
__device__ int     d_cnt[NN], d_offs[NN], d_deg[NN], d_cur[NN], d_csr[NE];
__device__ int     d_total;
__device__ float   d_dinv[NN], d_s[NN];
__device__ int     d_bstart[NG + 1];
__device__ float   d_pool[NG * HD];
__device__ float   d_o1[NG * 256];

__device__ __forceinline__ float warp_sum(float v) {
    #pragma unroll
    for (int o = 16; o; o >>= 1) v += __shfl_xor_sync(0xffffffffu, v, o);
    return v;
}

// ---- graph preprocessing ----
__global__ void k_init() {
    int i = blockIdx.x * blockDim.x + threadIdx.x;
    if (i < NN) d_cnt[i] = 0;
    if (i == 0) d_total = 0;
}
__global__ void k_count(const int* __restrict__ ei) {
    int e = blockIdx.x * blockDim.x + threadIdx.x;
    if (e < NE) atomicAdd(&d_cnt[ei[NE + e]], 1);
}
// slot allocation via global cursor — CSR order is irrelevant (commutative sums)
__global__ void k_offs() {
    int n = blockIdx.x * blockDim.x + threadIdx.x;
    if (n >= NN) return;
    int c = d_cnt[n];
    int st = atomicAdd(&d_total, c);
    d_offs[n] = st;
    d_cur[n] = st;
    d_deg[n] = c;
    d_dinv[n] = rsqrtf((float)(c + 1));
}
__global__ void k_fill(const int* __restrict__ ei) {
    int e = blockIdx.x * blockDim.x + threadIdx.x;
    if (e < NE) d_csr[atomicAdd(&d_cur[ei[NE + e]], 1)] = ei[e];
}

// layer-1 scalar aggregation (IN=1 makes conv1 rank-1)
__global__ void k_s(const float* __restrict__ x) {
    int n = blockIdx.x * blockDim.x + threadIdx.x;
    if (n >= NN) return;
    float dv = d_dinv[n];
    float acc = dv * x[n];
    int b = d_offs[n], e = b + d_deg[n];
    for (int j = b; j < e; j++) { int s = d_csr[j]; acc += d_dinv[s] * x[s]; }
    d_s[n] = dv * acc;
}

// W^T + fp16 hi/lo split: out[n*HD+k] = split(W[k*HD+n])
__global__ void k_wsplit(const float* __restrict__ W, int which) {
    __half* hi = (which == 2) ? d_w2hi : d_w3hi;
    __half* lo = (which == 2) ? d_w2lo : d_w3lo;
    __shared__ float tile[32][33];
    int bx = blockIdx.x * 32, by = blockIdx.y * 32;
    int tx = threadIdx.x, ty = threadIdx.y;
    for (int r = ty; r < 32; r += 8)
        tile[r][tx] = W[(size_t)(by + r) * HD + bx + tx];
    __syncthreads();
    for (int r = ty; r < 32; r += 8) {
        float w = tile[tx][r];
        __half h = __float2half_rn(w);
        size_t o = (size_t)(bx + r) * HD + by + tx;
        hi[o] = h;
        lo[o] = __float2half_rn(w - __half2float(h));
    }
}

// fused layer-1: h = act(LN(s*W1+b1)*g1 + be1), float4 vectorized
__global__ void k_ln1f(const float* __restrict__ W1, const float* __restrict__ b1,
                       const float* __restrict__ gam, const float* __restrict__ bet) {
    int n = blockIdx.x, tid = threadIdx.x;
    int wid = tid >> 5, lane = tid & 31;
    float sc = d_s[n];
    float4 w4 = reinterpret_cast<const float4*>(W1)[tid];
    float4 bb = reinterpret_cast<const float4*>(b1)[tid];
    float4 v;
    v.x = sc * w4.x + bb.x; v.y = sc * w4.y + bb.y;
    v.z = sc * w4.z + bb.z; v.w = sc * w4.w + bb.w;
    float s = v.x + v.y + v.z + v.w;
    float sq = v.x * v.x + v.y * v.y + v.z * v.z + v.w * v.w;
    s = warp_sum(s); sq = warp_sum(sq);
    __shared__ float shs[8], shq[8];
    if (lane == 0) { shs[wid] = s; shq[wid] = sq; }
    __syncthreads();
    if (wid == 0) {
        float a = (lane < 8) ? shs[lane] : 0.f;
        float b = (lane < 8) ? shq[lane] : 0.f;
        a = warp_sum(a); b = warp_sum(b);
        if (lane == 0) { shs[0] = a; shq[0] = b; }
    }
    __syncthreads();
    float mu = shs[0] * (1.f / HD);
    float var = shq[0] * (1.f / HD) - mu * mu;
    float r = rsqrtf(var + EPSV);
    float4 g4 = reinterpret_cast<const float4*>(gam)[tid];
    float4 e4 = reinterpret_cast<const float4*>(bet)[tid];
    float4 y;
    y.x = (v.x - mu) * r * g4.x + e4.x;
    y.y = (v.y - mu) * r * g4.y + e4.y;
    y.z = (v.z - mu) * r * g4.z + e4.z;
    y.w = (v.w - mu) * r * g4.w + e4.w;
    y.x = (y.x >= 0.f) ? y.x : SLOPE * y.x;
    y.y = (y.y >= 0.f) ? y.y : SLOPE * y.y;
    y.z = (y.z >= 0.f) ? y.z : SLOPE * y.z;
    y.w = (y.w >= 0.f) ? y.w : SLOPE * y.w;
    reinterpret_cast<float4*>(d_h)[(size_t)n * 256 + tid] = y;
}

// LN + LeakyReLU (layers 2/3), float4 vectorized
__global__ void k_ln_act(const float* __restrict__ bias,
                         const float* __restrict__ gam,
                         const float* __restrict__ bet) {
    int n = blockIdx.x, tid = threadIdx.x;
    int wid = tid >> 5, lane = tid & 31;
    float4 t4 = reinterpret_cast<const float4*>(d_t)[(size_t)n * 256 + tid];
    float4 bb = reinterpret_cast<const float4*>(bias)[tid];
    float4 v;
    v.x = t4.x + bb.x; v.y = t4.y + bb.y; v.z = t4.z + bb.z; v.w = t4.w + bb.w;
    float s = v.x + v.y + v.z + v.w;
    float sq = v.x * v.x + v.y * v.y + v.z * v.z + v.w * v.w;
    s = warp_sum(s); sq = warp_sum(sq);
    __shared__ float shs[8], shq[8];
    if (lane == 0) { shs[wid] = s; shq[wid] = sq; }
    __syncthreads();
    if (wid == 0) {
        float a = (lane < 8) ? shs[lane] : 0.f;
        float b = (lane < 8) ? shq[lane] : 0.f;
        a = warp_sum(a); b = warp_sum(b);
        if (lane == 0) { shs[0] = a; shq[0] = b; }
    }
    __syncthreads();
    float mu = shs[0] * (1.f / HD);
    float var = shq[0] * (1.f / HD) - mu * mu;
    float r = rsqrtf(var + EPSV);
    float4 g4 = reinterpret_cast<const float4*>(gam)[tid];
    float4 e4 = reinterpret_cast<const float4*>(bet)[tid];
    float4 y;
    y.x = (v.x - mu) * r * g4.x + e4.x;
    y.y = (v.y - mu) * r * g4.y + e4.y;
    y.z = (v.z - mu) * r * g4.z + e4.z;
    y.w = (v.w - mu) * r * g4.w + e4.w;
    y.x = (y.x >= 0.f) ? y.x : SLOPE * y.x;
    y.y = (y.y >= 0.f) ? y.y : SLOPE * y.y;
    y.z = (y.z >= 0.f) ? y.z : SLOPE * y.z;
    y.w = (y.w >= 0.f) ? y.w : SLOPE * y.w;
    reinterpret_cast<float4*>(d_h)[(size_t)n * 256 + tid] = y;
}

// aggregation of d_h -> fp16 hi/lo, float4 gather + half2 stores
__global__ void k_agg() {
    int dd = blockIdx.x, tid = threadIdx.x;
    float dv = d_dinv[dd];
    const float4* hb = reinterpret_cast<const float4*>(d_h);
    float4 a = hb[(size_t)dd * 256 + tid];
    float4 acc = make_float4(dv * a.x, dv * a.y, dv * a.z, dv * a.w);
    int b = d_offs[dd], e = b + d_deg[dd];
    for (int j = b; j < e; j++) {
        int s = d_csr[j];
        float w = d_dinv[s];
        float4 v = hb[(size_t)s * 256 + tid];
        acc.x += w * v.x; acc.y += w * v.y; acc.z += w * v.z; acc.w += w * v.w;
    }
    acc.x *= dv; acc.y *= dv; acc.z *= dv; acc.w *= dv;
    __half hx = __float2half_rn(acc.x), hy = __float2half_rn(acc.y);
    __half hz = __float2half_rn(acc.z), hw = __float2half_rn(acc.w);
    __half2* hi2 = reinterpret_cast<__half2*>(d_ahi) + (size_t)dd * 512 + tid * 2;
    __half2* lo2 = reinterpret_cast<__half2*>(d_alo) + (size_t)dd * 512 + tid * 2;
    hi2[0] = __halves2half2(hx, hy);
    hi2[1] = __halves2half2(hz, hw);
    lo2[0] = __halves2half2(__float2half_rn(acc.x - __half2float(hx)),
                            __float2half_rn(acc.y - __half2float(hy)));
    lo2[1] = __halves2half2(__float2half_rn(acc.z - __half2float(hz)),
                            __float2half_rn(acc.w - __half2float(hw)));
}

// ---- mma.sync GEMM: d_t = Agg @ W  (2 products: (a_hi+a_lo)*b_hi) ----
// BM=64 x BN=256, 256 threads (2x4 warps, warp tile 32x64), XOR swizzle,
// 4 stages x 24KB = 96KB -> 2 CTAs/SM. MMA:LDSM issue ratio 4.0.
#define BM 64
#define BN 256
#define BK 32
#define KIT (HD / BK)          // 32
#define STAGES 4
#define ARR_A (BM * 64)        // 4096 bytes per A array
#define ARR_BB (BN * 64)       // 16384 bytes for B array
#define STAGE_B (2 * ARR_A + ARR_BB)   // 24576 bytes per stage
#define GEMM_SMEM (STAGES * STAGE_B)   // 98304

__device__ __forceinline__ void cp16(uint32_t saddr, const void* g, int sz) {
    asm volatile("cp.async.cg.shared.global [%0], [%1], 16, %2;"
                 :: "r"(saddr), "l"(g), "r"(sz));
}
#define CP_COMMIT() asm volatile("cp.async.commit_group;" ::: "memory")
#define CP_WAIT2()  asm volatile("cp.async.wait_group 2;" ::: "memory")

#define LDSM4(r, addr)                                                          \
    asm volatile("ldmatrix.sync.aligned.m8n8.x4.shared.b16 {%0,%1,%2,%3}, [%4];"\
                 : "=r"((r)[0]), "=r"((r)[1]), "=r"((r)[2]), "=r"((r)[3])       \
                 : "r"(addr))

#define MMA16816(c, a, b0, b1)                                                  \
    asm volatile("mma.sync.aligned.m16n8k16.row.col.f32.f16.f16.f32 "           \
                 "{%0,%1,%2,%3}, {%4,%5,%6,%7}, {%8,%9}, {%0,%1,%2,%3};"        \
                 : "+f"((c)[0]), "+f"((c)[1]), "+f"((c)[2]), "+f"((c)[3])       \
                 : "r"((a)[0]), "r"((a)[1]), "r"((a)[2]), "r"((a)[3]),          \
                   "r"(b0), "r"(b1))

__device__ __forceinline__ void g_load_stage(
    int it, int s, uint32_t sbase, int tid, int m0, int n0,
    const __half* ahi, const __half* alo, const __half* bhi)
{
    int k0 = it * BK;
    uint32_t sb = sbase + s * STAGE_B;
    int row = tid >> 2, ch = tid & 3;              // row 0..63
    int p = ch ^ ((row >> 1) & 3);                 // XOR swizzle (64-row invariant)
    uint32_t so = (uint32_t)(row * 64 + p * 16);
    int gr = m0 + row;
    int asz = (gr < NN) ? 16 : 0;
    size_t aoff = ((size_t)((gr < NN) ? gr : 0) << 10) + k0 + ch * 8;
    cp16(sb + 0 * ARR_A + so, ahi + aoff, asz);
    cp16(sb + 1 * ARR_A + so, alo + aoff, asz);
    // B: 256 rows, 4 per thread at +64-row strides (swizzle p invariant)
    uint32_t bbase = sb + 2 * ARR_A + so;
    size_t boff = ((size_t)(n0 + row) << 10) + k0 + ch * 8;
    #pragma unroll
    for (int r = 0; r < 4; r++)
        cp16(bbase + r * 4096, bhi + boff + (size_t)r * 64 * HD, 16);
}

__global__ void __launch_bounds__(256) k_gemm(int which) {
    extern __shared__ char smem[];
    const __half* whi = (which == 2) ? d_w2hi : d_w3hi;
    uint32_t sbase = (uint32_t)__cvta_generic_to_shared(smem);
    int tid = threadIdx.x;
    int lane = tid & 31, wid = tid >> 5;
    int warp_m = wid & 1, warp_n = wid >> 1;       // 2 x 4 warps
    int m0 = blockIdx.y * BM, n0 = blockIdx.x * BN;   // N fastest-varying

    float acc[2][8][4];
    #pragma unroll
    for (int mt = 0; mt < 2; mt++)
        #pragma unroll
        for (int nt = 0; nt < 8; nt++)
            #pragma unroll
            for (int q = 0; q < 4; q++) acc[mt][nt][q] = 0.f;

    int la = lane & 15;
    uint32_t a_row = (uint32_t)((warp_m * 32 + la) * 64);
    int swa = (la >> 1) & 3;
    int acb = lane >> 4;
    int rb = (lane & 7) | ((lane >> 4) << 3);
    uint32_t b_row = (uint32_t)((warp_n * 64 + rb) * 64);
    int swb = (rb >> 1) & 3;
    int bcb = (lane >> 3) & 1;

    g_load_stage(0, 0, sbase, tid, m0, n0, d_ahi, d_alo, whi);
    CP_COMMIT();
    g_load_stage(1, 1, sbase, tid, m0, n0, d_ahi, d_alo, whi);
    CP_COMMIT();
    g_load_stage(2, 2, sbase, tid, m0, n0, d_ahi, d_alo, whi);
    CP_COMMIT();

    for (int it = 0; it < KIT; ++it) {
        CP_WAIT2();
        __syncthreads();
        if (it + 3 < KIT)
            g_load_stage(it + 3, (it + 3) & 3, sbase, tid, m0, n0, d_ahi, d_alo, whi);
        CP_COMMIT();

        uint32_t sb = sbase + (it & 3) * STAGE_B;
        #pragma unroll
        for (int kk = 0; kk < 2; kk++) {
            int pa = (acb | (kk << 1)) ^ swa;
            int pb = (bcb | (kk << 1)) ^ swb;
            uint32_t bh[4][4];
            uint32_t bbase = sb + 2 * ARR_A + b_row + (uint32_t)(pb * 16);
            #pragma unroll
            for (int p = 0; p < 4; p++)
                LDSM4(bh[p], bbase + (uint32_t)(p * 1024));
            uint32_t ad0 = sb + a_row + (uint32_t)(pa * 16);
            uint32_t ad1 = ad0 + 1024;
            // hi pass
            {
                uint32_t ah[4], ah2[4];
                LDSM4(ah, ad0);
                LDSM4(ah2, ad1);
                #pragma unroll
                for (int nt = 0; nt < 8; nt++) {
                    int p = nt >> 1, q = (nt & 1) * 2;
                    MMA16816(acc[0][nt], ah, bh[p][q], bh[p][q + 1]);
                    MMA16816(acc[1][nt], ah2, bh[p][q], bh[p][q + 1]);
                }
            }
            // lo pass (reuses hi fragment registers)
            {
                uint32_t al[4], al2[4];
                LDSM4(al, ad0 + ARR_A);
                LDSM4(al2, ad1 + ARR_A);
                #pragma unroll
                for (int nt = 0; nt < 8; nt++) {
                    int p = nt >> 1, q = (nt & 1) * 2;
                    MMA16816(acc[0][nt], al, bh[p][q], bh[p][q + 1]);
                    MMA16816(acc[1][nt], al2, bh[p][q], bh[p][q + 1]);
                }
            }
        }
        __syncthreads();
    }

    int mrow = m0 + warp_m * 32 + (lane >> 2);
    int ncol = n0 + warp_n * 64 + (lane & 3) * 2;
    #pragma unroll
    for (int mt = 0; mt < 2; mt++)
        #pragma unroll
        for (int nt = 0; nt < 8; nt++) {
            int r1 = mrow + mt * 16, r2 = r1 + 8;
            int c = ncol + nt * 8;
            if (r1 < NN) {
                float2 v = make_float2(acc[mt][nt][0], acc[mt][nt][1]);
                *reinterpret_cast<float2*>(&d_t[((size_t)r1 << 10) + c]) = v;
            }
            if (r2 < NN) {
                float2 v = make_float2(acc[mt][nt][2], acc[mt][nt][3]);
                *reinterpret_cast<float2*>(&d_t[((size_t)r2 << 10) + c]) = v;
            }
        }
}

// ---- pooling + FC head ----
__global__ void k_bstart(const int* __restrict__ batch) {
    int g = threadIdx.x;
    if (g > NG) return;
    int lo = 0, hi = NN;
    while (lo < hi) { int m = (lo + hi) >> 1; if (batch[m] < g) lo = m + 1; else hi = m; }
    d_bstart[g] = lo;
}
__global__ void k_pool() {
    int g = blockIdx.x, col = blockIdx.y * 128 + threadIdx.x;
    int b = d_bstart[g], e = d_bstart[g + 1];
    float s = 0.f;
    for (int n = b; n < e; n++) s += d_h[(size_t)n * HD + col];
    d_pool[g * HD + col] = s / fmaxf((float)(e - b), 1.0f);
}
__global__ void k_fc1(const float* __restrict__ fw1, const float* __restrict__ fb1) {
    int g = blockIdx.x, j = threadIdx.x;
    float acc = fb1[j];
    for (int k = 0; k < HD; k++) acc += d_pool[g * HD + k] * fw1[k * 256 + j];
    d_o1[g * 256 + j] = acc;
}
__global__ void k_fc2(const float* __restrict__ fw2, const float* __restrict__ fb2,
                      float* __restrict__ out) {
    int g = blockIdx.x, j = threadIdx.x;
    float v = d_o1[g * 256 + j] * fw2[j];
    v = warp_sum(v);
    __shared__ float sh[8];
    if ((j & 31) == 0) sh[j >> 5] = v;
    __syncthreads();
    if (j == 0) {
        float a = 0.f;
        for (int w = 0; w < 8; w++) a += sh[w];
        out[g] = a + fb2[0];
    }
}

extern "C" void kernel_launch(void* const* d_in, const int* in_sizes, int n_in,
                              void* d_out, int out_size) {
    const float* x    = (const float*)d_in[0];
    const int*   ei   = (const int*)  d_in[1];
    const int*   bat  = (const int*)  d_in[2];
    const float* W1   = (const float*)d_in[3];
    const float* b1   = (const float*)d_in[4];
    const float* W2   = (const float*)d_in[5];
    const float* b2   = (const float*)d_in[6];
    const float* W3   = (const float*)d_in[7];
    const float* b3   = (const float*)d_in[8];
    const float* g1   = (const float*)d_in[9];
    const float* be1  = (const float*)d_in[10];
    const float* g2   = (const float*)d_in[11];
    const float* be2  = (const float*)d_in[12];
    const float* g3   = (const float*)d_in[13];
    const float* be3  = (const float*)d_in[14];
    const float* fw1  = (const float*)d_in[15];
    const float* fb1  = (const float*)d_in[16];
    const float* fw2  = (const float*)d_in[17];
    const float* fb2  = (const float*)d_in[18];
    float* out = (float*)d_out;

    cudaFuncSetAttribute(k_gemm, cudaFuncAttributeMaxDynamicSharedMemorySize, GEMM_SMEM);

    k_init<<<(NN + 255) / 256, 256>>>();
    k_count<<<(NE + 255) / 256, 256>>>(ei);
    k_offs<<<(NN + 255) / 256, 256>>>();
    k_fill<<<(NE + 255) / 256, 256>>>(ei);
    k_s<<<(NN + 255) / 256, 256>>>(x);
    dim3 wg(HD / 32, HD / 32), wb(32, 8);
    k_wsplit<<<wg, wb>>>(W2, 2);
    k_wsplit<<<wg, wb>>>(W3, 3);

    dim3 gg(HD / BN, (NN + BM - 1) / BM);   // N fastest -> A-tile L2 reuse

    k_ln1f<<<NN, 256>>>(W1, b1, g1, be1);
    k_agg<<<NN, 256>>>();
    k_gemm<<<gg, 256, GEMM_SMEM>>>(2);
    k_ln_act<<<NN, 256>>>(b2, g2, be2);
    k_agg<<<NN, 256>>>();
    k_gemm<<<gg, 256, GEMM_SMEM>>>(3);
    k_ln_act<<<NN, 256>>>(b3, g3, be3);

    k_bstart<<<1, 32>>>(bat);
    k_pool<<<dim3(NG, HD / 128), 128>>>();
    k_fc1<<<NG, 256>>>(fw1, fb1);
    k_fc2<<<NG, 256>>>(fw2, fb2, out);
}